// round 15
// baseline (speedup 1.0000x reference)
#include <cuda_runtime.h>
#include <cuda_bf16.h>
#include <math.h>
#include <stdint.h>

// Shapes: B=16, N=512, D=256, H=8, DK=32, C=16
#define BB 16
#define NN 512
#define DD 256
#define HH 8
#define DKH 32
#define CC 16

__device__ float g_bufQ[BB * NN * DD];
__device__ float g_bufK[BB * NN * DD];
__device__ float g_bufV[BB * NN * DD];
__device__ float g_bufO[BB * NN * DD];
__device__ float g_bufX[BB * NN * DD];
__device__ float g_bufE[BB * NN * DD];   // rounded embeddings
__device__ float g_Wr[10 * DD * DD];     // rounded weights
__device__ float g_rbias[BB * DD];
__device__ float g_G[BB * CC * DD];
__device__ float g_CNT[BB * CC];

__device__ __forceinline__ float gelu_f(float x) {
    return 0.5f * x * (1.0f + erff(x * 0.7071067811865475f));
}

// exp(x) on the FMA/ALU pipes (no MUFU). ~1.2e-7 rel error.
__device__ __forceinline__ float fast_exp(float x) {
    float y = x * 1.4426950408889634f;
    y = fmaxf(y, -126.0f);
    float f = rintf(y);
    float z = y - f;
    float p = 1.5403530393381609e-4f;
    p = fmaf(p, z, 1.3333558146428443e-3f);
    p = fmaf(p, z, 9.6181291076284772e-3f);
    p = fmaf(p, z, 5.5504108664821580e-2f);
    p = fmaf(p, z, 2.4022650695910072e-1f);
    p = fmaf(p, z, 6.9314718055994531e-1f);
    p = fmaf(p, z, 1.0f);
    int e = (int)f;
    float s = __int_as_float((e + 127) << 23);
    return p * s;
}

__device__ __forceinline__ uint32_t f2tf32(float x) {
    uint32_t u;
    asm("cvt.rna.tf32.f32 %0, %1;" : "=r"(u) : "f"(x));
    return u;
}

__device__ __forceinline__ void mma_tf32(float c[4],
    uint32_t a0, uint32_t a1, uint32_t a2, uint32_t a3,
    uint32_t b0, uint32_t b1)
{
    asm volatile(
        "mma.sync.aligned.m16n8k8.row.col.f32.tf32.tf32.f32 "
        "{%0,%1,%2,%3},{%4,%5,%6,%7},{%8,%9},{%0,%1,%2,%3};"
        : "+f"(c[0]), "+f"(c[1]), "+f"(c[2]), "+f"(c[3])
        : "r"(a0), "r"(a1), "r"(a2), "r"(a3), "r"(b0), "r"(b1));
}

// ---------------------------------------------------------------------------
// prep: round 10 weight matrices (65536 el each) + E (2M el) to tf32 (rna).
// ---------------------------------------------------------------------------
struct PrepArgs {
    const float* w[10];
    const float* E;
};

#define WELEMS (DD * DD)            // 65536
#define WTOTAL (10 * WELEMS)        // 655360
#define EELEMS (BB * NN * DD)       // 2097152
#define PREP_GROUPS ((WTOTAL + EELEMS) / 4)   // 688128

__global__ __launch_bounds__(256) void prep_kernel(PrepArgs a)
{
    int g = blockIdx.x * 256 + threadIdx.x;
    if (g >= PREP_GROUPS) return;
    int idx = g * 4;
    if (idx < WTOTAL) {
        int w = idx >> 16, off = idx & (WELEMS - 1);
        float4 v = *(const float4*)&a.w[w][off];
        uint4 r = make_uint4(f2tf32(v.x), f2tf32(v.y), f2tf32(v.z), f2tf32(v.w));
        *(uint4*)&g_Wr[(size_t)w * WELEMS + off] = r;
    } else {
        int off = idx - WTOTAL;
        float4 v = *(const float4*)&a.E[off];
        uint4 r = make_uint4(f2tf32(v.x), f2tf32(v.y), f2tf32(v.z), f2tf32(v.w));
        *(uint4*)&g_bufE[off] = r;
    }
}

// ---------------------------------------------------------------------------
// tf32 tensor-core GEMM, double-buffered.
// ARAW=1: A is pre-rounded -> raw uint4 staging (requires AIN=0).
// W is ALWAYS pre-rounded -> raw uint4 staging.
// TF32OUT: round output (scaled by oscale) for downstream raw consumers.
// ---------------------------------------------------------------------------
#define GBM 128
#define GBN 128
#define GBK 16

template <int AIN, int AOUT, int BMODE, int TF32OUT, int ARAW>
__device__ __forceinline__ void gemm_tf32_body(
    const float* __restrict__ A, const float* __restrict__ W,
    const float* __restrict__ bias, float* __restrict__ C,
    int M, int N, int K, int bm, int bn, float oscale)
{
    __shared__ uint32_t As[2][GBM][GBK + 4];
    __shared__ uint32_t Ws[2][GBK][GBN + 8];

    const int t    = threadIdx.x;
    const int lane = t & 31;
    const int wid  = t >> 5;
    const int wm   = (wid & 1) * 64;
    const int wn   = (wid >> 1) * 32;

    const int ar = t >> 1, ac = (t & 1) * 8;
    const int wr = t >> 4, wc = (t & 15) * 8;
    const int lq = lane >> 2;
    const int lr = lane & 3;

    float c[4][4][4];
    #pragma unroll
    for (int mt = 0; mt < 4; mt++)
        #pragma unroll
        for (int nt = 0; nt < 4; nt++)
            #pragma unroll
            for (int i = 0; i < 4; i++) c[mt][nt][i] = 0.0f;

    const int NIT = K / GBK;

    {
        if (ARAW) {
            uint4 a0 = *(const uint4*)&A[(size_t)(bm + ar) * K + ac];
            uint4 a1 = *(const uint4*)&A[(size_t)(bm + ar) * K + ac + 4];
            *(uint4*)&As[0][ar][ac]     = a0;
            *(uint4*)&As[0][ar][ac + 4] = a1;
        } else {
            float4 a0 = *(const float4*)&A[(size_t)(bm + ar) * K + ac];
            float4 a1 = *(const float4*)&A[(size_t)(bm + ar) * K + ac + 4];
            if (AIN) {
                a0.x = gelu_f(a0.x); a0.y = gelu_f(a0.y); a0.z = gelu_f(a0.z); a0.w = gelu_f(a0.w);
                a1.x = gelu_f(a1.x); a1.y = gelu_f(a1.y); a1.z = gelu_f(a1.z); a1.w = gelu_f(a1.w);
            }
            As[0][ar][ac + 0] = f2tf32(a0.x); As[0][ar][ac + 1] = f2tf32(a0.y);
            As[0][ar][ac + 2] = f2tf32(a0.z); As[0][ar][ac + 3] = f2tf32(a0.w);
            As[0][ar][ac + 4] = f2tf32(a1.x); As[0][ar][ac + 5] = f2tf32(a1.y);
            As[0][ar][ac + 6] = f2tf32(a1.z); As[0][ar][ac + 7] = f2tf32(a1.w);
        }
        uint4 w0 = *(const uint4*)&W[(size_t)wr * N + bn + wc];
        uint4 w1 = *(const uint4*)&W[(size_t)wr * N + bn + wc + 4];
        *(uint4*)&Ws[0][wr][wc]     = w0;
        *(uint4*)&Ws[0][wr][wc + 4] = w1;
    }
    __syncthreads();

    for (int it = 0; it < NIT; it++) {
        const int cur = it & 1, nxt = cur ^ 1;
        const bool has = (it + 1 < NIT);
        const int k0n = (it + 1) * GBK;

        float4 na0, na1;
        uint4 ua0, ua1, nw0, nw1;
        if (has) {
            if (ARAW) {
                ua0 = *(const uint4*)&A[(size_t)(bm + ar) * K + k0n + ac];
                ua1 = *(const uint4*)&A[(size_t)(bm + ar) * K + k0n + ac + 4];
            } else {
                na0 = *(const float4*)&A[(size_t)(bm + ar) * K + k0n + ac];
                na1 = *(const float4*)&A[(size_t)(bm + ar) * K + k0n + ac + 4];
            }
            nw0 = *(const uint4*)&W[(size_t)(k0n + wr) * N + bn + wc];
            nw1 = *(const uint4*)&W[(size_t)(k0n + wr) * N + bn + wc + 4];
        }

        #pragma unroll
        for (int ks = 0; ks < GBK; ks += 8) {
            uint32_t af[4][4];
            #pragma unroll
            for (int mt = 0; mt < 4; mt++) {
                int r = wm + mt * 16 + lq;
                af[mt][0] = As[cur][r    ][ks + lr];
                af[mt][1] = As[cur][r + 8][ks + lr];
                af[mt][2] = As[cur][r    ][ks + lr + 4];
                af[mt][3] = As[cur][r + 8][ks + lr + 4];
            }
            uint32_t bf[4][2];
            #pragma unroll
            for (int nt = 0; nt < 4; nt++) {
                int nc = wn + nt * 8 + lq;
                bf[nt][0] = Ws[cur][ks + lr    ][nc];
                bf[nt][1] = Ws[cur][ks + lr + 4][nc];
            }
            #pragma unroll
            for (int mt = 0; mt < 4; mt++)
                #pragma unroll
                for (int nt = 0; nt < 4; nt++)
                    mma_tf32(c[mt][nt], af[mt][0], af[mt][1], af[mt][2], af[mt][3],
                             bf[nt][0], bf[nt][1]);
        }

        if (has) {
            if (ARAW) {
                *(uint4*)&As[nxt][ar][ac]     = ua0;
                *(uint4*)&As[nxt][ar][ac + 4] = ua1;
            } else {
                if (AIN) {
                    na0.x = gelu_f(na0.x); na0.y = gelu_f(na0.y); na0.z = gelu_f(na0.z); na0.w = gelu_f(na0.w);
                    na1.x = gelu_f(na1.x); na1.y = gelu_f(na1.y); na1.z = gelu_f(na1.z); na1.w = gelu_f(na1.w);
                }
                As[nxt][ar][ac + 0] = f2tf32(na0.x); As[nxt][ar][ac + 1] = f2tf32(na0.y);
                As[nxt][ar][ac + 2] = f2tf32(na0.z); As[nxt][ar][ac + 3] = f2tf32(na0.w);
                As[nxt][ar][ac + 4] = f2tf32(na1.x); As[nxt][ar][ac + 5] = f2tf32(na1.y);
                As[nxt][ar][ac + 6] = f2tf32(na1.z); As[nxt][ar][ac + 7] = f2tf32(na1.w);
            }
            *(uint4*)&Ws[nxt][wr][wc]     = nw0;
            *(uint4*)&Ws[nxt][wr][wc + 4] = nw1;
            __syncthreads();
        }
    }

    #pragma unroll
    for (int mt = 0; mt < 4; mt++) {
        int row0 = bm + wm + mt * 16 + lq;
        int row1 = row0 + 8;
        #pragma unroll
        for (int nt = 0; nt < 4; nt++) {
            int col = bn + wn + nt * 8 + lr * 2;
            float v0 = c[mt][nt][0], v1 = c[mt][nt][1];
            float v2 = c[mt][nt][2], v3 = c[mt][nt][3];
            if (BMODE == 1) {
                float b0 = bias[col], b1 = bias[col + 1];
                v0 += b0; v1 += b1; v2 += b0; v3 += b1;
            }
            if (BMODE == 2) {
                const float* bb0 = bias + (size_t)(row0 >> 9) * N + col;
                v0 += bb0[0]; v1 += bb0[1];
                const float* bb1 = bias + (size_t)(row1 >> 9) * N + col;
                v2 += bb1[0]; v3 += bb1[1];
            }
            if (AOUT) { v0 = gelu_f(v0); v1 = gelu_f(v1); v2 = gelu_f(v2); v3 = gelu_f(v3); }
            if (TF32OUT) {
                v0 = __uint_as_float(f2tf32(v0 * oscale));
                v1 = __uint_as_float(f2tf32(v1 * oscale));
                v2 = __uint_as_float(f2tf32(v2 * oscale));
                v3 = __uint_as_float(f2tf32(v3 * oscale));
            }
            *(float2*)&C[(size_t)row0 * N + col] = make_float2(v0, v1);
            *(float2*)&C[(size_t)row1 * N + col] = make_float2(v2, v3);
        }
    }
}

template <int AIN, int AOUT, int BMODE, int TF32OUT, int ARAW>
__global__ __launch_bounds__(256) void gemm_tf32_kernel(
    const float* __restrict__ A, const float* __restrict__ W,
    const float* __restrict__ bias, float* __restrict__ C,
    int M, int N, int K)
{
    gemm_tf32_body<AIN, AOUT, BMODE, TF32OUT, ARAW>(A, W, bias, C, M, N, K,
                                        blockIdx.x * GBM, blockIdx.y * GBN, 1.0f);
}

// QKV fused: A and W pre-rounded; Q output prescaled + rounded.
__global__ __launch_bounds__(256) void gemm_tf32_qkv_kernel(
    const float* __restrict__ A,
    const float* __restrict__ W0, const float* __restrict__ W1, const float* __restrict__ W2,
    float* __restrict__ C0, float* __restrict__ C1, float* __restrict__ C2,
    int M, int N, int K)
{
    const float* W = (blockIdx.z == 0) ? W0 : (blockIdx.z == 1) ? W1 : W2;
    float*       C = (blockIdx.z == 0) ? C0 : (blockIdx.z == 1) ? C1 : C2;
    const float oscale = (blockIdx.z == 0) ? 0.17677669529663688f : 1.0f;
    gemm_tf32_body<0, 0, 0, 1, 1>(A, W, nullptr, C, M, N, K,
                                  blockIdx.x * GBM, blockIdx.y * GBN, oscale);
}

// ---------------------------------------------------------------------------
// Fused attention v9 (R13) + rounded output (feeds Wo GEMM raw staging).
// ---------------------------------------------------------------------------
#define SCT 132
#define ATTN_SMEM_WORDS 15264
#define ATTN_SMEM_BYTES (ATTN_SMEM_WORDS * 4)

__global__ __launch_bounds__(256, 3) void attn_kernel(
    const float* __restrict__ Qp, const float* __restrict__ Kp,
    const float* __restrict__ Vp, float* __restrict__ Op)
{
    extern __shared__ uint32_t smu[];
    uint32_t* qs = smu;             // [32][36]
    uint32_t* ks = smu + 1152;      // [128][36]
    uint32_t* vs = smu + 5760;      // [128][40]
    uint32_t* sc = smu + 10880;     // [32][132]
    float*   rsp = (float*)(smu + 15104);
    float*   rs  = (float*)(smu + 15232);

    const int t    = threadIdx.x;
    const int lane = t & 31;
    const int w    = t >> 5;
    const int qb = blockIdx.x * 32;
    const int h  = blockIdx.y;
    const int b  = blockIdx.z;

    const size_t baseQ  = ((size_t)(b * NN + qb)) * DD + h * DKH;
    const size_t baseKV = ((size_t)(b * NN)) * DD + h * DKH;

    {
        int r = t >> 3, c = (t & 7) * 4;
        *(uint4*)&qs[r * 36 + c] = *(const uint4*)&Qp[baseQ + (size_t)r * DD + c];
    }
    __syncthreads();

    const int lq = lane >> 2;
    const int lr = lane & 3;
    const int mb = (w & 1) * 16;
    const int nqb = (w >> 1) * 32;
    const int nvb = (w >> 1) * 8;

    uint32_t qa[4][4];
    #pragma unroll
    for (int kk = 0; kk < 4; kk++) {
        qa[kk][0] = qs[(mb + lq)     * 36 + kk * 8 + lr];
        qa[kk][1] = qs[(mb + 8 + lq) * 36 + kk * 8 + lr];
        qa[kk][2] = qs[(mb + lq)     * 36 + kk * 8 + lr + 4];
        qa[kk][3] = qs[(mb + 8 + lq) * 36 + kk * 8 + lr + 4];
    }

    float rlo = 0.0f, rhi = 0.0f;
    float oc[4] = {0.0f, 0.0f, 0.0f, 0.0f};

    #pragma unroll 1
    for (int kt = 0; kt < 4; kt++) {
        const int kb = kt * 128;
        __syncthreads();
        for (int i = t; i < 1024; i += 256) {
            int r = i >> 3, c = (i & 7) * 4;
            *(uint4*)&ks[r * 36 + c] =
                *(const uint4*)&Kp[baseKV + (size_t)(kb + r) * DD + c];
        }
        for (int i = t; i < 1024; i += 256) {
            int r = i >> 3, c = (i & 7) * 4;
            *(uint4*)&vs[r * 40 + c] =
                *(const uint4*)&Vp[baseKV + (size_t)(kb + r) * DD + c];
        }
        __syncthreads();

        #pragma unroll
        for (int nt = 0; nt < 4; nt++) {
            const int nb = nqb + nt * 8;
            float c4[4] = {0.0f, 0.0f, 0.0f, 0.0f};
            #pragma unroll
            for (int kk = 0; kk < 4; kk++) {
                uint32_t b0 = ks[(nb + lq) * 36 + kk * 8 + lr];
                uint32_t b1 = ks[(nb + lq) * 36 + kk * 8 + lr + 4];
                mma_tf32(c4, qa[kk][0], qa[kk][1], qa[kk][2], qa[kk][3], b0, b1);
            }
            float e0 = fast_exp(c4[0]);
            float e1 = fast_exp(c4[1]);
            float e2 = fast_exp(c4[2]);
            float e3 = fast_exp(c4[3]);
            rlo += e0 + e1;
            rhi += e2 + e3;
            *(uint2*)&sc[(mb + lq)     * SCT + nb + 2 * lr] = make_uint2(f2tf32(e0), f2tf32(e1));
            *(uint2*)&sc[(mb + 8 + lq) * SCT + nb + 2 * lr] = make_uint2(f2tf32(e2), f2tf32(e3));
        }
        __syncthreads();

        #pragma unroll
        for (int kk = 0; kk < 16; kk++) {
            const int kk8 = kk * 8;
            uint32_t a0 = sc[(mb + lq)     * SCT + kk8 + lr];
            uint32_t a1 = sc[(mb + 8 + lq) * SCT + kk8 + lr];
            uint32_t a2 = sc[(mb + lq)     * SCT + kk8 + lr + 4];
            uint32_t a3 = sc[(mb + 8 + lq) * SCT + kk8 + lr + 4];
            uint32_t b0 = vs[(kk8 + lr)     * 40 + nvb + lq];
            uint32_t b1 = vs[(kk8 + lr + 4) * 40 + nvb + lq];
            mma_tf32(oc, a0, a1, a2, a3, b0, b1);
        }
    }

    rlo += __shfl_xor_sync(0xFFFFFFFFu, rlo, 1);
    rlo += __shfl_xor_sync(0xFFFFFFFFu, rlo, 2);
    rhi += __shfl_xor_sync(0xFFFFFFFFu, rhi, 1);
    rhi += __shfl_xor_sync(0xFFFFFFFFu, rhi, 2);
    if (lr == 0) {
        rsp[w * 16 + lq]     = rlo;
        rsp[w * 16 + 8 + lq] = rhi;
    }
    __syncthreads();
    if (t < 32) {
        int mt = t >> 4, r = t & 15;
        rs[t] = rsp[mt * 16 + r] + rsp[(mt + 2) * 16 + r]
              + rsp[(mt + 4) * 16 + r] + rsp[(mt + 6) * 16 + r];
    }
    __syncthreads();

    {
        float inv0 = 1.0f / rs[mb + lq];
        float inv1 = 1.0f / rs[mb + 8 + lq];
        int col = nvb + 2 * lr;
        // rounded output: Wo GEMM stages A raw (numerics == CVT-at-staging)
        *(uint2*)&Op[baseQ + (size_t)(mb + lq)     * DD + col] =
            make_uint2(f2tf32(oc[0] * inv0), f2tf32(oc[1] * inv0));
        *(uint2*)&Op[baseQ + (size_t)(mb + 8 + lq) * DD + col] =
            make_uint2(f2tf32(oc[2] * inv1), f2tf32(oc[3] * inv1));
    }
}

// ---------------------------------------------------------------------------
// Fused aggregate chain (unchanged from R14).
// ---------------------------------------------------------------------------
__global__ __launch_bounds__(1024) void aggr_kernel(
    const float* __restrict__ X,
    const float* __restrict__ resW, const float* __restrict__ resb,
    const float* __restrict__ ffW1, const float* __restrict__ ffb1,
    float* __restrict__ rbias)
{
    __shared__ float part[4][DD];
    __shared__ float ag[DD];
    __shared__ float ar[DD];
    const int b = blockIdx.x;
    const int t = threadIdx.x & 255;
    const int p = threadIdx.x >> 8;

    float s = 0.0f;
    const float* base = X + (size_t)b * NN * DD + (size_t)p * 128 * DD + t;
    #pragma unroll 8
    for (int n = 0; n < 128; n++) s += base[(size_t)n * DD];
    part[p][t] = s;
    __syncthreads();
    if (p == 0)
        ag[t] = gelu_f((part[0][t] + part[1][t] + part[2][t] + part[3][t]) * (1.0f / (float)NN));
    __syncthreads();

    s = 0.0f;
    #pragma unroll 8
    for (int k = p * 64; k < p * 64 + 64; k++)
        s = fmaf(ag[k], resW[(size_t)k * DD + t], s);
    part[p][t] = s;
    __syncthreads();
    if (p == 0)
        ar[t] = gelu_f(part[0][t] + part[1][t] + part[2][t] + part[3][t] + resb[t]);
    __syncthreads();

    s = 0.0f;
    #pragma unroll 8
    for (int k = p * 64; k < p * 64 + 64; k++)
        s = fmaf(ar[k], ffW1[(size_t)k * DD + t], s);
    part[p][t] = s;
    __syncthreads();
    if (p == 0)
        rbias[b * DD + t] = part[0][t] + part[1][t] + part[2][t] + part[3][t] + ffb1[t];
}

// ---------------------------------------------------------------------------
// class_sum (unchanged from R14).
// ---------------------------------------------------------------------------
__global__ __launch_bounds__(256) void class_sum_kernel(
    const float* __restrict__ F, const int* __restrict__ lab,
    float* __restrict__ G, float* __restrict__ CNT)
{
    __shared__ int slab[NN];
    __shared__ int idx[NN];
    __shared__ int scnt;
    const int c = blockIdx.x;
    const int b = blockIdx.y;
    const int t = threadIdx.x;

    for (int n = t; n < NN; n += 256) slab[n] = lab[b * NN + n];
    __syncthreads();

    if (t < 32) {
        int cnt = 0;
        for (int ch = 0; ch < NN / 32; ch++) {
            int n = ch * 32 + t;
            bool m = (slab[n] == c);
            unsigned mask = __ballot_sync(0xFFFFFFFFu, m);
            if (m) idx[cnt + __popc(mask & ((1u << t) - 1u))] = n;
            cnt += __popc(mask);
        }
        if (t == 0) scnt = cnt;
    }
    __syncthreads();

    const int m = scnt;
    const float* Fb = F + (size_t)b * NN * DD;
    float s = 0.0f;
    int i = 0;
    for (; i + 4 <= m; i += 4) {
        int n0 = idx[i], n1 = idx[i+1], n2 = idx[i+2], n3 = idx[i+3];
        float v0 = Fb[(size_t)n0 * DD + t];
        float v1 = Fb[(size_t)n1 * DD + t];
        float v2 = Fb[(size_t)n2 * DD + t];
        float v3 = Fb[(size_t)n3 * DD + t];
        s += (v0 + v1) + (v2 + v3);
    }
    for (; i < m; i++) s += Fb[(size_t)idx[i] * DD + t];

    G[((size_t)b * CC + c) * DD + t] = s;
    if (t == 0) CNT[b * CC + c] = (float)m;
}

// ---------------------------------------------------------------------------
// proto_out v2 (unchanged from R14).
// ---------------------------------------------------------------------------
__global__ __launch_bounds__(256) void proto_out_kernel(
    const float* __restrict__ F, const float* __restrict__ G,
    const float* __restrict__ CNT, const int* __restrict__ lab,
    float* __restrict__ out)
{
    __shared__ float gs[CC * DD];
    __shared__ float cnt_s[CC];
    const int nb = blockIdx.x * 32;
    const int b  = blockIdx.y;
    const int t  = threadIdx.x;
    const int w  = t >> 5, lane = t & 31;

    for (int i = t; i < CC * DD; i += 256)
        gs[i] = G[(size_t)b * CC * DD + i];
    if (t < CC) cnt_s[t] = CNT[b * CC + t];
    __syncthreads();

    const float4* gs4 = (const float4*)gs;

    #pragma unroll
    for (int rr = 0; rr < 4; rr++) {
        const int n = nb + w * 4 + rr;
        const float* f = F + ((size_t)b * NN + n) * DD;
        float4 fa = *(const float4*)&f[lane * 4];
        float4 fb = *(const float4*)&f[128 + lane * 4];

        float sd = fa.x*fa.x + fa.y*fa.y + fa.z*fa.z + fa.w*fa.w
                 + fb.x*fb.x + fb.y*fb.y + fb.z*fb.z + fb.w*fb.w;

        float dp[CC];
        #pragma unroll
        for (int c = 0; c < CC; c++) {
            float4 ga = gs4[c * 64 + lane];
            float4 gb = gs4[c * 64 + 32 + lane];
            dp[c] = fa.x*ga.x + fa.y*ga.y + fa.z*ga.z + fa.w*ga.w
                  + fb.x*gb.x + fb.y*gb.y + fb.z*gb.z + fb.w*gb.w;
        }

        #pragma unroll
        for (int o = 16; o; o >>= 1) {
            sd += __shfl_xor_sync(0xFFFFFFFFu, sd, o);
            #pragma unroll
            for (int c = 0; c < CC; c++)
                dp[c] += __shfl_xor_sync(0xFFFFFFFFu, dp[c], o);
        }

        if (lane < CC) {
            const int labn = lab[b * NN + n];
            float same = (labn == lane) ? 1.0f : 0.0f;
            out[((size_t)b * NN + n) * CC + lane] =
                (dp[lane] - same * sd) / (cnt_s[lane] - same);
        }
    }
}

// ---------------------------------------------------------------------------
extern "C" void kernel_launch(void* const* d_in, const int* in_sizes, int n_in,
                              void* d_out, int out_size)
{
    const float* E    = (const float*)d_in[0];
    const int*   lab  = (const int*)  d_in[1];
    const float* Wq0  = (const float*)d_in[2];
    const float* Wk0  = (const float*)d_in[3];
    const float* Wv0  = (const float*)d_in[4];
    const float* Wo0  = (const float*)d_in[5];
    const float* Wq1  = (const float*)d_in[6];
    const float* Wk1  = (const float*)d_in[7];
    const float* Wv1  = (const float*)d_in[8];
    const float* Wo1  = (const float*)d_in[9];
    const float* resW = (const float*)d_in[10];
    const float* resb = (const float*)d_in[11];
    const float* ffW1 = (const float*)d_in[12];
    const float* ffb1 = (const float*)d_in[13];
    const float* ffW2 = (const float*)d_in[14];
    const float* ffb2 = (const float*)d_in[15];
    float* out = (float*)d_out;

    float *bQ, *bK, *bV, *bO, *bX, *bE, *Wr, *rbias, *G, *CNT;
    cudaGetSymbolAddress((void**)&bQ,    g_bufQ);
    cudaGetSymbolAddress((void**)&bK,    g_bufK);
    cudaGetSymbolAddress((void**)&bV,    g_bufV);
    cudaGetSymbolAddress((void**)&bO,    g_bufO);
    cudaGetSymbolAddress((void**)&bX,    g_bufX);
    cudaGetSymbolAddress((void**)&bE,    g_bufE);
    cudaGetSymbolAddress((void**)&Wr,    g_Wr);
    cudaGetSymbolAddress((void**)&rbias, g_rbias);
    cudaGetSymbolAddress((void**)&G,     g_G);
    cudaGetSymbolAddress((void**)&CNT,   g_CNT);

    cudaFuncSetAttribute(attn_kernel,
                         cudaFuncAttributeMaxDynamicSharedMemorySize,
                         ATTN_SMEM_BYTES);

    const int M = BB * NN;                 // 8192
    dim3 gBig(M / GBM, DD / GBN);          // (64, 2)
    dim3 gQKV(M / GBM, DD / GBN, 3);       // (64, 2, 3)
    dim3 gAttn(NN / 32, HH, BB);           // (16, 8, 16)

    // ---- prep: round weights + E ----
    PrepArgs pa;
    pa.w[0] = Wq0; pa.w[1] = Wk0; pa.w[2] = Wv0; pa.w[3] = Wo0;
    pa.w[4] = Wq1; pa.w[5] = Wk1; pa.w[6] = Wv1; pa.w[7] = Wo1;
    pa.w[8] = ffW1 + (size_t)DD * DD;      // ffW1 second half (E path)
    pa.w[9] = ffW2;
    pa.E = E;
    prep_kernel<<<(PREP_GROUPS + 255) / 256, 256>>>(pa);

    const float* rWq0 = Wr + 0 * WELEMS;
    const float* rWk0 = Wr + 1 * WELEMS;
    const float* rWv0 = Wr + 2 * WELEMS;
    const float* rWo0 = Wr + 3 * WELEMS;
    const float* rWq1 = Wr + 4 * WELEMS;
    const float* rWk1 = Wr + 5 * WELEMS;
    const float* rWv1 = Wr + 6 * WELEMS;
    const float* rWo1 = Wr + 7 * WELEMS;
    const float* rFF1 = Wr + 8 * WELEMS;
    const float* rFF2 = Wr + 9 * WELEMS;

    // ---- MHA 0 ----
    gemm_tf32_qkv_kernel<<<gQKV, 256>>>(bE, rWq0, rWk0, rWv0, bQ, bK, bV, M, DD, DD);
    attn_kernel<<<gAttn, 256, ATTN_SMEM_BYTES>>>(bQ, bK, bV, bO);
    // Wo0: gelu + round (feeds qkv1 raw)
    gemm_tf32_kernel<0, 1, 0, 1, 1><<<gBig, 256>>>(bO, rWo0, nullptr, bX, M, DD, DD);

    // ---- MHA 1 ----
    gemm_tf32_qkv_kernel<<<gQKV, 256>>>(bX, rWq1, rWk1, rWv1, bQ, bK, bV, M, DD, DD);
    attn_kernel<<<gAttn, 256, ATTN_SMEM_BYTES>>>(bQ, bK, bV, bO);
    // Wo1: plain fp32 output (feeds aggr)
    gemm_tf32_kernel<0, 0, 0, 0, 1><<<gBig, 256>>>(bO, rWo1, nullptr, bX, M, DD, DD);

    // ---- aggregate path ----
    aggr_kernel<<<BB, 1024>>>(bX, resW, resb, ffW1, ffb1, rbias);
    // ff1: gelu-in on ORIGINAL E (cvt path), gelu-out + round (feeds ff2 raw)
    gemm_tf32_kernel<1, 1, 2, 1, 0><<<gBig, 256>>>(E, rFF1, rbias, bQ, M, DD, DD);
    // ff2: raw A + raw W, fp32 output
    gemm_tf32_kernel<0, 0, 1, 0, 1><<<gBig, 256>>>(bQ, rFF2, ffb2, bK, M, DD, DD);

    // ---- prototypical scoring ----
    class_sum_kernel<<<dim3(CC, BB), 256>>>(bK, lab, G, CNT);
    proto_out_kernel<<<dim3(NN / 32, BB), 256>>>(bK, G, CNT, lab, out);
}

// round 16
// speedup vs baseline: 1.0376x; 1.0376x over previous
#include <cuda_runtime.h>
#include <cuda_bf16.h>
#include <math.h>
#include <stdint.h>

// Shapes: B=16, N=512, D=256, H=8, DK=32, C=16
#define BB 16
#define NN 512
#define DD 256
#define HH 8
#define DKH 32
#define CC 16

__device__ float g_bufQ[BB * NN * DD];
__device__ float g_bufK[BB * NN * DD];
__device__ float g_bufV[BB * NN * DD];
__device__ float g_bufO[BB * NN * DD];
__device__ float g_bufX[BB * NN * DD];
__device__ float g_bufH[BB * NN * DD];   // gelu(E) @ ffW1[256:] (pre-bias)
__device__ float g_rbias[BB * DD];
__device__ float g_G[BB * CC * DD];
__device__ float g_CNT[BB * CC];

__device__ __forceinline__ float gelu_f(float x) {
    return 0.5f * x * (1.0f + erff(x * 0.7071067811865475f));
}

// exp(x) on the FMA/ALU pipes (no MUFU). ~1.2e-7 rel error.
__device__ __forceinline__ float fast_exp(float x) {
    float y = x * 1.4426950408889634f;
    y = fmaxf(y, -126.0f);
    float f = rintf(y);
    float z = y - f;
    float p = 1.5403530393381609e-4f;
    p = fmaf(p, z, 1.3333558146428443e-3f);
    p = fmaf(p, z, 9.6181291076284772e-3f);
    p = fmaf(p, z, 5.5504108664821580e-2f);
    p = fmaf(p, z, 2.4022650695910072e-1f);
    p = fmaf(p, z, 6.9314718055994531e-1f);
    p = fmaf(p, z, 1.0f);
    int e = (int)f;
    float s = __int_as_float((e + 127) << 23);
    return p * s;
}

__device__ __forceinline__ uint32_t f2tf32(float x) {
    uint32_t u;
    asm("cvt.rna.tf32.f32 %0, %1;" : "=r"(u) : "f"(x));
    return u;
}

__device__ __forceinline__ void mma_tf32(float c[4],
    uint32_t a0, uint32_t a1, uint32_t a2, uint32_t a3,
    uint32_t b0, uint32_t b1)
{
    asm volatile(
        "mma.sync.aligned.m16n8k8.row.col.f32.tf32.tf32.f32 "
        "{%0,%1,%2,%3},{%4,%5,%6,%7},{%8,%9},{%0,%1,%2,%3};"
        : "+f"(c[0]), "+f"(c[1]), "+f"(c[2]), "+f"(c[3])
        : "r"(a0), "r"(a1), "r"(a2), "r"(a3), "r"(b0), "r"(b1));
}

// ---------------------------------------------------------------------------
// tf32 tensor-core GEMM, double-buffered (R14 layout, rna CVT staging).
// ABIAS=1: A-staging computes cvt(gelu(A + abias[row/512][k])) — used by ff2.
// TF32OUT: round output (scaled by oscale) for attention inputs.
// ---------------------------------------------------------------------------
#define GBM 128
#define GBN 128
#define GBK 16

template <int AIN, int AOUT, int BMODE, int TF32OUT, int ABIAS>
__device__ __forceinline__ void gemm_tf32_body(
    const float* __restrict__ A, const float* __restrict__ W,
    const float* __restrict__ bias, const float* __restrict__ abias,
    float* __restrict__ C,
    int M, int N, int K, int bm, int bn, float oscale)
{
    __shared__ uint32_t As[2][GBM][GBK + 4];
    __shared__ uint32_t Ws[2][GBK][GBN + 8];

    const int t    = threadIdx.x;
    const int lane = t & 31;
    const int wid  = t >> 5;
    const int wm   = (wid & 1) * 64;
    const int wn   = (wid >> 1) * 32;

    const int ar = t >> 1, ac = (t & 1) * 8;
    const int wr = t >> 4, wc = (t & 15) * 8;
    const int lq = lane >> 2;
    const int lr = lane & 3;

    float c[4][4][4];
    #pragma unroll
    for (int mt = 0; mt < 4; mt++)
        #pragma unroll
        for (int nt = 0; nt < 4; nt++)
            #pragma unroll
            for (int i = 0; i < 4; i++) c[mt][nt][i] = 0.0f;

    const int NIT = K / GBK;
    const int arow = bm + ar;
    const float* abrow = ABIAS ? (abias + (size_t)(arow >> 9) * K) : nullptr;

    {
        float4 a0 = *(const float4*)&A[(size_t)arow * K + ac];
        float4 a1 = *(const float4*)&A[(size_t)arow * K + ac + 4];
        if (ABIAS) {
            float4 b0 = *(const float4*)&abrow[ac];
            float4 b1 = *(const float4*)&abrow[ac + 4];
            a0.x = gelu_f(a0.x + b0.x); a0.y = gelu_f(a0.y + b0.y);
            a0.z = gelu_f(a0.z + b0.z); a0.w = gelu_f(a0.w + b0.w);
            a1.x = gelu_f(a1.x + b1.x); a1.y = gelu_f(a1.y + b1.y);
            a1.z = gelu_f(a1.z + b1.z); a1.w = gelu_f(a1.w + b1.w);
        } else if (AIN) {
            a0.x = gelu_f(a0.x); a0.y = gelu_f(a0.y); a0.z = gelu_f(a0.z); a0.w = gelu_f(a0.w);
            a1.x = gelu_f(a1.x); a1.y = gelu_f(a1.y); a1.z = gelu_f(a1.z); a1.w = gelu_f(a1.w);
        }
        As[0][ar][ac + 0] = f2tf32(a0.x); As[0][ar][ac + 1] = f2tf32(a0.y);
        As[0][ar][ac + 2] = f2tf32(a0.z); As[0][ar][ac + 3] = f2tf32(a0.w);
        As[0][ar][ac + 4] = f2tf32(a1.x); As[0][ar][ac + 5] = f2tf32(a1.y);
        As[0][ar][ac + 6] = f2tf32(a1.z); As[0][ar][ac + 7] = f2tf32(a1.w);

        float4 w0 = *(const float4*)&W[(size_t)wr * N + bn + wc];
        float4 w1 = *(const float4*)&W[(size_t)wr * N + bn + wc + 4];
        Ws[0][wr][wc + 0] = f2tf32(w0.x); Ws[0][wr][wc + 1] = f2tf32(w0.y);
        Ws[0][wr][wc + 2] = f2tf32(w0.z); Ws[0][wr][wc + 3] = f2tf32(w0.w);
        Ws[0][wr][wc + 4] = f2tf32(w1.x); Ws[0][wr][wc + 5] = f2tf32(w1.y);
        Ws[0][wr][wc + 6] = f2tf32(w1.z); Ws[0][wr][wc + 7] = f2tf32(w1.w);
    }
    __syncthreads();

    for (int it = 0; it < NIT; it++) {
        const int cur = it & 1, nxt = cur ^ 1;
        const bool has = (it + 1 < NIT);
        const int k0n = (it + 1) * GBK;

        float4 na0, na1, nw0, nw1;
        if (has) {
            na0 = *(const float4*)&A[(size_t)arow * K + k0n + ac];
            na1 = *(const float4*)&A[(size_t)arow * K + k0n + ac + 4];
            nw0 = *(const float4*)&W[(size_t)(k0n + wr) * N + bn + wc];
            nw1 = *(const float4*)&W[(size_t)(k0n + wr) * N + bn + wc + 4];
        }

        #pragma unroll
        for (int ks = 0; ks < GBK; ks += 8) {
            uint32_t af[4][4];
            #pragma unroll
            for (int mt = 0; mt < 4; mt++) {
                int r = wm + mt * 16 + lq;
                af[mt][0] = As[cur][r    ][ks + lr];
                af[mt][1] = As[cur][r + 8][ks + lr];
                af[mt][2] = As[cur][r    ][ks + lr + 4];
                af[mt][3] = As[cur][r + 8][ks + lr + 4];
            }
            uint32_t bf[4][2];
            #pragma unroll
            for (int nt = 0; nt < 4; nt++) {
                int nc = wn + nt * 8 + lq;
                bf[nt][0] = Ws[cur][ks + lr    ][nc];
                bf[nt][1] = Ws[cur][ks + lr + 4][nc];
            }
            #pragma unroll
            for (int mt = 0; mt < 4; mt++)
                #pragma unroll
                for (int nt = 0; nt < 4; nt++)
                    mma_tf32(c[mt][nt], af[mt][0], af[mt][1], af[mt][2], af[mt][3],
                             bf[nt][0], bf[nt][1]);
        }

        if (has) {
            if (ABIAS) {
                float4 b0 = *(const float4*)&abrow[k0n + ac];
                float4 b1 = *(const float4*)&abrow[k0n + ac + 4];
                na0.x = gelu_f(na0.x + b0.x); na0.y = gelu_f(na0.y + b0.y);
                na0.z = gelu_f(na0.z + b0.z); na0.w = gelu_f(na0.w + b0.w);
                na1.x = gelu_f(na1.x + b1.x); na1.y = gelu_f(na1.y + b1.y);
                na1.z = gelu_f(na1.z + b1.z); na1.w = gelu_f(na1.w + b1.w);
            } else if (AIN) {
                na0.x = gelu_f(na0.x); na0.y = gelu_f(na0.y); na0.z = gelu_f(na0.z); na0.w = gelu_f(na0.w);
                na1.x = gelu_f(na1.x); na1.y = gelu_f(na1.y); na1.z = gelu_f(na1.z); na1.w = gelu_f(na1.w);
            }
            As[nxt][ar][ac + 0] = f2tf32(na0.x); As[nxt][ar][ac + 1] = f2tf32(na0.y);
            As[nxt][ar][ac + 2] = f2tf32(na0.z); As[nxt][ar][ac + 3] = f2tf32(na0.w);
            As[nxt][ar][ac + 4] = f2tf32(na1.x); As[nxt][ar][ac + 5] = f2tf32(na1.y);
            As[nxt][ar][ac + 6] = f2tf32(na1.z); As[nxt][ar][ac + 7] = f2tf32(na1.w);
            Ws[nxt][wr][wc + 0] = f2tf32(nw0.x); Ws[nxt][wr][wc + 1] = f2tf32(nw0.y);
            Ws[nxt][wr][wc + 2] = f2tf32(nw0.z); Ws[nxt][wr][wc + 3] = f2tf32(nw0.w);
            Ws[nxt][wr][wc + 4] = f2tf32(nw1.x); Ws[nxt][wr][wc + 5] = f2tf32(nw1.y);
            Ws[nxt][wr][wc + 6] = f2tf32(nw1.z); Ws[nxt][wr][wc + 7] = f2tf32(nw1.w);
            __syncthreads();
        }
    }

    #pragma unroll
    for (int mt = 0; mt < 4; mt++) {
        int row0 = bm + wm + mt * 16 + lq;
        int row1 = row0 + 8;
        #pragma unroll
        for (int nt = 0; nt < 4; nt++) {
            int col = bn + wn + nt * 8 + lr * 2;
            float v0 = c[mt][nt][0], v1 = c[mt][nt][1];
            float v2 = c[mt][nt][2], v3 = c[mt][nt][3];
            if (BMODE == 1) {
                float b0 = bias[col], b1 = bias[col + 1];
                v0 += b0; v1 += b1; v2 += b0; v3 += b1;
            }
            if (BMODE == 2) {
                const float* bb0 = bias + (size_t)(row0 >> 9) * N + col;
                v0 += bb0[0]; v1 += bb0[1];
                const float* bb1 = bias + (size_t)(row1 >> 9) * N + col;
                v2 += bb1[0]; v3 += bb1[1];
            }
            if (AOUT) { v0 = gelu_f(v0); v1 = gelu_f(v1); v2 = gelu_f(v2); v3 = gelu_f(v3); }
            if (TF32OUT) {
                v0 = __uint_as_float(f2tf32(v0 * oscale));
                v1 = __uint_as_float(f2tf32(v1 * oscale));
                v2 = __uint_as_float(f2tf32(v2 * oscale));
                v3 = __uint_as_float(f2tf32(v3 * oscale));
            }
            *(float2*)&C[(size_t)row0 * N + col] = make_float2(v0, v1);
            *(float2*)&C[(size_t)row1 * N + col] = make_float2(v2, v3);
        }
    }
}

template <int AIN, int AOUT, int BMODE, int TF32OUT, int ABIAS>
__global__ __launch_bounds__(256) void gemm_tf32_kernel(
    const float* __restrict__ A, const float* __restrict__ W,
    const float* __restrict__ bias, const float* __restrict__ abias,
    float* __restrict__ C, int M, int N, int K)
{
    gemm_tf32_body<AIN, AOUT, BMODE, TF32OUT, ABIAS>(A, W, bias, abias, C, M, N, K,
                                        blockIdx.x * GBM, blockIdx.y * GBN, 1.0f);
}

// QKV fused. z<3: Q/K/V projections (tf32-rounded out, Q prescaled).
// z==3 (layer-0 launch only): Hraw = gelu(E) @ W3, plain fp32 out.
__global__ __launch_bounds__(256) void gemm_tf32_qkv_kernel(
    const float* __restrict__ A,
    const float* __restrict__ W0, const float* __restrict__ W1,
    const float* __restrict__ W2, const float* __restrict__ W3,
    float* __restrict__ C0, float* __restrict__ C1,
    float* __restrict__ C2, float* __restrict__ C3,
    int M, int N, int K)
{
    const int z = blockIdx.z;
    if (z == 3) {
        gemm_tf32_body<1, 0, 0, 0, 0>(A, W3, nullptr, nullptr, C3, M, N, K,
                                      blockIdx.x * GBM, blockIdx.y * GBN, 1.0f);
        return;
    }
    const float* W = (z == 0) ? W0 : (z == 1) ? W1 : W2;
    float*       C = (z == 0) ? C0 : (z == 1) ? C1 : C2;
    const float oscale = (z == 0) ? 0.17677669529663688f : 1.0f;
    gemm_tf32_body<0, 0, 0, 1, 0>(A, W, nullptr, nullptr, C, M, N, K,
                                  blockIdx.x * GBM, blockIdx.y * GBN, oscale);
}

// ---------------------------------------------------------------------------
// Fused attention v9 (unchanged from R14) — per-key-tile QK->exp->PV, 3 CTAs/SM.
// ---------------------------------------------------------------------------
#define SCT 132
#define ATTN_SMEM_WORDS 15264
#define ATTN_SMEM_BYTES (ATTN_SMEM_WORDS * 4)

__global__ __launch_bounds__(256, 3) void attn_kernel(
    const float* __restrict__ Qp, const float* __restrict__ Kp,
    const float* __restrict__ Vp, float* __restrict__ Op)
{
    extern __shared__ uint32_t smu[];
    uint32_t* qs = smu;             // [32][36]
    uint32_t* ks = smu + 1152;      // [128][36]
    uint32_t* vs = smu + 5760;      // [128][40]
    uint32_t* sc = smu + 10880;     // [32][132]
    float*   rsp = (float*)(smu + 15104);
    float*   rs  = (float*)(smu + 15232);

    const int t    = threadIdx.x;
    const int lane = t & 31;
    const int w    = t >> 5;
    const int qb = blockIdx.x * 32;
    const int h  = blockIdx.y;
    const int b  = blockIdx.z;

    const size_t baseQ  = ((size_t)(b * NN + qb)) * DD + h * DKH;
    const size_t baseKV = ((size_t)(b * NN)) * DD + h * DKH;

    {
        int r = t >> 3, c = (t & 7) * 4;
        *(uint4*)&qs[r * 36 + c] = *(const uint4*)&Qp[baseQ + (size_t)r * DD + c];
    }
    __syncthreads();

    const int lq = lane >> 2;
    const int lr = lane & 3;
    const int mb = (w & 1) * 16;
    const int nqb = (w >> 1) * 32;
    const int nvb = (w >> 1) * 8;

    uint32_t qa[4][4];
    #pragma unroll
    for (int kk = 0; kk < 4; kk++) {
        qa[kk][0] = qs[(mb + lq)     * 36 + kk * 8 + lr];
        qa[kk][1] = qs[(mb + 8 + lq) * 36 + kk * 8 + lr];
        qa[kk][2] = qs[(mb + lq)     * 36 + kk * 8 + lr + 4];
        qa[kk][3] = qs[(mb + 8 + lq) * 36 + kk * 8 + lr + 4];
    }

    float rlo = 0.0f, rhi = 0.0f;
    float oc[4] = {0.0f, 0.0f, 0.0f, 0.0f};

    #pragma unroll 1
    for (int kt = 0; kt < 4; kt++) {
        const int kb = kt * 128;
        __syncthreads();
        for (int i = t; i < 1024; i += 256) {
            int r = i >> 3, c = (i & 7) * 4;
            *(uint4*)&ks[r * 36 + c] =
                *(const uint4*)&Kp[baseKV + (size_t)(kb + r) * DD + c];
        }
        for (int i = t; i < 1024; i += 256) {
            int r = i >> 3, c = (i & 7) * 4;
            *(uint4*)&vs[r * 40 + c] =
                *(const uint4*)&Vp[baseKV + (size_t)(kb + r) * DD + c];
        }
        __syncthreads();

        #pragma unroll
        for (int nt = 0; nt < 4; nt++) {
            const int nb = nqb + nt * 8;
            float c4[4] = {0.0f, 0.0f, 0.0f, 0.0f};
            #pragma unroll
            for (int kk = 0; kk < 4; kk++) {
                uint32_t b0 = ks[(nb + lq) * 36 + kk * 8 + lr];
                uint32_t b1 = ks[(nb + lq) * 36 + kk * 8 + lr + 4];
                mma_tf32(c4, qa[kk][0], qa[kk][1], qa[kk][2], qa[kk][3], b0, b1);
            }
            float e0 = fast_exp(c4[0]);
            float e1 = fast_exp(c4[1]);
            float e2 = fast_exp(c4[2]);
            float e3 = fast_exp(c4[3]);
            rlo += e0 + e1;
            rhi += e2 + e3;
            *(uint2*)&sc[(mb + lq)     * SCT + nb + 2 * lr] = make_uint2(f2tf32(e0), f2tf32(e1));
            *(uint2*)&sc[(mb + 8 + lq) * SCT + nb + 2 * lr] = make_uint2(f2tf32(e2), f2tf32(e3));
        }
        __syncthreads();

        #pragma unroll
        for (int kk = 0; kk < 16; kk++) {
            const int kk8 = kk * 8;
            uint32_t a0 = sc[(mb + lq)     * SCT + kk8 + lr];
            uint32_t a1 = sc[(mb + 8 + lq) * SCT + kk8 + lr];
            uint32_t a2 = sc[(mb + lq)     * SCT + kk8 + lr + 4];
            uint32_t a3 = sc[(mb + 8 + lq) * SCT + kk8 + lr + 4];
            uint32_t b0 = vs[(kk8 + lr)     * 40 + nvb + lq];
            uint32_t b1 = vs[(kk8 + lr + 4) * 40 + nvb + lq];
            mma_tf32(oc, a0, a1, a2, a3, b0, b1);
        }
    }

    rlo += __shfl_xor_sync(0xFFFFFFFFu, rlo, 1);
    rlo += __shfl_xor_sync(0xFFFFFFFFu, rlo, 2);
    rhi += __shfl_xor_sync(0xFFFFFFFFu, rhi, 1);
    rhi += __shfl_xor_sync(0xFFFFFFFFu, rhi, 2);
    if (lr == 0) {
        rsp[w * 16 + lq]     = rlo;
        rsp[w * 16 + 8 + lq] = rhi;
    }
    __syncthreads();
    if (t < 32) {
        int mt = t >> 4, r = t & 15;
        rs[t] = rsp[mt * 16 + r] + rsp[(mt + 2) * 16 + r]
              + rsp[(mt + 4) * 16 + r] + rsp[(mt + 6) * 16 + r];
    }
    __syncthreads();

    {
        float inv0 = 1.0f / rs[mb + lq];
        float inv1 = 1.0f / rs[mb + 8 + lq];
        int col = nvb + 2 * lr;
        *(float2*)&Op[baseQ + (size_t)(mb + lq)     * DD + col] =
            make_float2(oc[0] * inv0, oc[1] * inv0);
        *(float2*)&Op[baseQ + (size_t)(mb + 8 + lq) * DD + col] =
            make_float2(oc[2] * inv1, oc[3] * inv1);
    }
}

// ---------------------------------------------------------------------------
// Fused aggregate chain (unchanged from R14).
// ---------------------------------------------------------------------------
__global__ __launch_bounds__(1024) void aggr_kernel(
    const float* __restrict__ X,
    const float* __restrict__ resW, const float* __restrict__ resb,
    const float* __restrict__ ffW1, const float* __restrict__ ffb1,
    float* __restrict__ rbias)
{
    __shared__ float part[4][DD];
    __shared__ float ag[DD];
    __shared__ float ar[DD];
    const int b = blockIdx.x;
    const int t = threadIdx.x & 255;
    const int p = threadIdx.x >> 8;

    float s = 0.0f;
    const float* base = X + (size_t)b * NN * DD + (size_t)p * 128 * DD + t;
    #pragma unroll 8
    for (int n = 0; n < 128; n++) s += base[(size_t)n * DD];
    part[p][t] = s;
    __syncthreads();
    if (p == 0)
        ag[t] = gelu_f((part[0][t] + part[1][t] + part[2][t] + part[3][t]) * (1.0f / (float)NN));
    __syncthreads();

    s = 0.0f;
    #pragma unroll 8
    for (int k = p * 64; k < p * 64 + 64; k++)
        s = fmaf(ag[k], resW[(size_t)k * DD + t], s);
    part[p][t] = s;
    __syncthreads();
    if (p == 0)
        ar[t] = gelu_f(part[0][t] + part[1][t] + part[2][t] + part[3][t] + resb[t]);
    __syncthreads();

    s = 0.0f;
    #pragma unroll 8
    for (int k = p * 64; k < p * 64 + 64; k++)
        s = fmaf(ar[k], ffW1[(size_t)k * DD + t], s);
    part[p][t] = s;
    __syncthreads();
    if (p == 0)
        rbias[b * DD + t] = part[0][t] + part[1][t] + part[2][t] + part[3][t] + ffb1[t];
}

// ---------------------------------------------------------------------------
// class_sum (unchanged from R14).
// ---------------------------------------------------------------------------
__global__ __launch_bounds__(256) void class_sum_kernel(
    const float* __restrict__ F, const int* __restrict__ lab,
    float* __restrict__ G, float* __restrict__ CNT)
{
    __shared__ int slab[NN];
    __shared__ int idx[NN];
    __shared__ int scnt;
    const int c = blockIdx.x;
    const int b = blockIdx.y;
    const int t = threadIdx.x;

    for (int n = t; n < NN; n += 256) slab[n] = lab[b * NN + n];
    __syncthreads();

    if (t < 32) {
        int cnt = 0;
        for (int ch = 0; ch < NN / 32; ch++) {
            int n = ch * 32 + t;
            bool m = (slab[n] == c);
            unsigned mask = __ballot_sync(0xFFFFFFFFu, m);
            if (m) idx[cnt + __popc(mask & ((1u << t) - 1u))] = n;
            cnt += __popc(mask);
        }
        if (t == 0) scnt = cnt;
    }
    __syncthreads();

    const int m = scnt;
    const float* Fb = F + (size_t)b * NN * DD;
    float s = 0.0f;
    int i = 0;
    for (; i + 4 <= m; i += 4) {
        int n0 = idx[i], n1 = idx[i+1], n2 = idx[i+2], n3 = idx[i+3];
        float v0 = Fb[(size_t)n0 * DD + t];
        float v1 = Fb[(size_t)n1 * DD + t];
        float v2 = Fb[(size_t)n2 * DD + t];
        float v3 = Fb[(size_t)n3 * DD + t];
        s += (v0 + v1) + (v2 + v3);
    }
    for (; i < m; i++) s += Fb[(size_t)idx[i] * DD + t];

    G[((size_t)b * CC + c) * DD + t] = s;
    if (t == 0) CNT[b * CC + c] = (float)m;
}

// ---------------------------------------------------------------------------
// proto_out v2 (unchanged from R14).
// ---------------------------------------------------------------------------
__global__ __launch_bounds__(256) void proto_out_kernel(
    const float* __restrict__ F, const float* __restrict__ G,
    const float* __restrict__ CNT, const int* __restrict__ lab,
    float* __restrict__ out)
{
    __shared__ float gs[CC * DD];
    __shared__ float cnt_s[CC];
    const int nb = blockIdx.x * 32;
    const int b  = blockIdx.y;
    const int t  = threadIdx.x;
    const int w  = t >> 5, lane = t & 31;

    for (int i = t; i < CC * DD; i += 256)
        gs[i] = G[(size_t)b * CC * DD + i];
    if (t < CC) cnt_s[t] = CNT[b * CC + t];
    __syncthreads();

    const float4* gs4 = (const float4*)gs;

    #pragma unroll
    for (int rr = 0; rr < 4; rr++) {
        const int n = nb + w * 4 + rr;
        const float* f = F + ((size_t)b * NN + n) * DD;
        float4 fa = *(const float4*)&f[lane * 4];
        float4 fb = *(const float4*)&f[128 + lane * 4];

        float sd = fa.x*fa.x + fa.y*fa.y + fa.z*fa.z + fa.w*fa.w
                 + fb.x*fb.x + fb.y*fb.y + fb.z*fb.z + fb.w*fb.w;

        float dp[CC];
        #pragma unroll
        for (int c = 0; c < CC; c++) {
            float4 ga = gs4[c * 64 + lane];
            float4 gb = gs4[c * 64 + 32 + lane];
            dp[c] = fa.x*ga.x + fa.y*ga.y + fa.z*ga.z + fa.w*ga.w
                  + fb.x*gb.x + fb.y*gb.y + fb.z*gb.z + fb.w*gb.w;
        }

        #pragma unroll
        for (int o = 16; o; o >>= 1) {
            sd += __shfl_xor_sync(0xFFFFFFFFu, sd, o);
            #pragma unroll
            for (int c = 0; c < CC; c++)
                dp[c] += __shfl_xor_sync(0xFFFFFFFFu, dp[c], o);
        }

        if (lane < CC) {
            const int labn = lab[b * NN + n];
            float same = (labn == lane) ? 1.0f : 0.0f;
            out[((size_t)b * NN + n) * CC + lane] =
                (dp[lane] - same * sd) / (cnt_s[lane] - same);
        }
    }
}

// ---------------------------------------------------------------------------
extern "C" void kernel_launch(void* const* d_in, const int* in_sizes, int n_in,
                              void* d_out, int out_size)
{
    const float* E    = (const float*)d_in[0];
    const int*   lab  = (const int*)  d_in[1];
    const float* Wq0  = (const float*)d_in[2];
    const float* Wk0  = (const float*)d_in[3];
    const float* Wv0  = (const float*)d_in[4];
    const float* Wo0  = (const float*)d_in[5];
    const float* Wq1  = (const float*)d_in[6];
    const float* Wk1  = (const float*)d_in[7];
    const float* Wv1  = (const float*)d_in[8];
    const float* Wo1  = (const float*)d_in[9];
    const float* resW = (const float*)d_in[10];
    const float* resb = (const float*)d_in[11];
    const float* ffW1 = (const float*)d_in[12];
    const float* ffb1 = (const float*)d_in[13];
    const float* ffW2 = (const float*)d_in[14];
    const float* ffb2 = (const float*)d_in[15];
    float* out = (float*)d_out;

    float *bQ, *bK, *bV, *bO, *bX, *bH, *rbias, *G, *CNT;
    cudaGetSymbolAddress((void**)&bQ,    g_bufQ);
    cudaGetSymbolAddress((void**)&bK,    g_bufK);
    cudaGetSymbolAddress((void**)&bV,    g_bufV);
    cudaGetSymbolAddress((void**)&bO,    g_bufO);
    cudaGetSymbolAddress((void**)&bX,    g_bufX);
    cudaGetSymbolAddress((void**)&bH,    g_bufH);
    cudaGetSymbolAddress((void**)&rbias, g_rbias);
    cudaGetSymbolAddress((void**)&G,     g_G);
    cudaGetSymbolAddress((void**)&CNT,   g_CNT);

    cudaFuncSetAttribute(attn_kernel,
                         cudaFuncAttributeMaxDynamicSharedMemorySize,
                         ATTN_SMEM_BYTES);

    const int M = BB * NN;                 // 8192
    dim3 gBig(M / GBM, DD / GBN);          // (64, 2)
    dim3 gQKV0(M / GBM, DD / GBN, 4);      // (64, 2, 4): Q,K,V + ff1-H
    dim3 gQKV1(M / GBM, DD / GBN, 3);      // (64, 2, 3)
    dim3 gAttn(NN / 32, HH, BB);           // (16, 8, 16)

    const float* ffW1hi = ffW1 + (size_t)DD * DD;

    // ---- MHA 0 (+ independent ff1 GEMM riding as z==3) ----
    gemm_tf32_qkv_kernel<<<gQKV0, 256>>>(E, Wq0, Wk0, Wv0, ffW1hi,
                                         bQ, bK, bV, bH, M, DD, DD);
    attn_kernel<<<gAttn, 256, ATTN_SMEM_BYTES>>>(bQ, bK, bV, bO);
    gemm_tf32_kernel<0, 1, 0, 0, 0><<<gBig, 256>>>(bO, Wo0, nullptr, nullptr, bX, M, DD, DD);

    // ---- MHA 1 ----
    gemm_tf32_qkv_kernel<<<gQKV1, 256>>>(bX, Wq1, Wk1, Wv1, nullptr,
                                         bQ, bK, bV, nullptr, M, DD, DD);
    attn_kernel<<<gAttn, 256, ATTN_SMEM_BYTES>>>(bQ, bK, bV, bO);
    gemm_tf32_kernel<0, 0, 0, 0, 0><<<gBig, 256>>>(bO, Wo1, nullptr, nullptr, bX, M, DD, DD);

    // ---- aggregate path ----
    aggr_kernel<<<BB, 1024>>>(bX, resW, resb, ffW1, ffb1, rbias);
    // ff2: A-staging applies gelu(H + rbias) (bias+gelu deferred from ff1)
    gemm_tf32_kernel<0, 0, 1, 0, 1><<<gBig, 256>>>(bH, ffW2, ffb2, rbias, bK, M, DD, DD);

    // ---- prototypical scoring ----
    class_sum_kernel<<<dim3(CC, BB), 256>>>(bK, lab, G, CNT);
    proto_out_kernel<<<dim3(NN / 32, BB), 256>>>(bK, G, CNT, lab, out);
}

// round 17
// speedup vs baseline: 1.0474x; 1.0094x over previous
#include <cuda_runtime.h>
#include <cuda_bf16.h>
#include <math.h>
#include <stdint.h>

// Shapes: B=16, N=512, D=256, H=8, DK=32, C=16
#define BB 16
#define NN 512
#define DD 256
#define HH 8
#define DKH 32
#define CC 16

__device__ float g_bufQ[BB * NN * DD];
__device__ float g_bufK[BB * NN * DD];
__device__ float g_bufV[BB * NN * DD];
__device__ float g_bufO[BB * NN * DD];
__device__ float g_bufX[BB * NN * DD];
__device__ float g_bufH[BB * NN * DD];   // gelu(E) @ ffW1[256:] (pre-bias)
__device__ float g_rbias[BB * DD];
__device__ float g_G[BB * CC * DD];
__device__ float g_CNT[BB * CC];

__device__ __forceinline__ float gelu_f(float x) {
    return 0.5f * x * (1.0f + erff(x * 0.7071067811865475f));
}

// exp(x) on the FMA/ALU pipes (no MUFU). ~1.2e-7 rel error.
__device__ __forceinline__ float fast_exp(float x) {
    float y = x * 1.4426950408889634f;
    y = fmaxf(y, -126.0f);
    float f = rintf(y);
    float z = y - f;
    float p = 1.5403530393381609e-4f;
    p = fmaf(p, z, 1.3333558146428443e-3f);
    p = fmaf(p, z, 9.6181291076284772e-3f);
    p = fmaf(p, z, 5.5504108664821580e-2f);
    p = fmaf(p, z, 2.4022650695910072e-1f);
    p = fmaf(p, z, 6.9314718055994531e-1f);
    p = fmaf(p, z, 1.0f);
    int e = (int)f;
    float s = __int_as_float((e + 127) << 23);
    return p * s;
}

__device__ __forceinline__ uint32_t f2tf32(float x) {
    uint32_t u;
    asm("cvt.rna.tf32.f32 %0, %1;" : "=r"(u) : "f"(x));
    return u;
}

__device__ __forceinline__ void mma_tf32(float c[4],
    uint32_t a0, uint32_t a1, uint32_t a2, uint32_t a3,
    uint32_t b0, uint32_t b1)
{
    asm volatile(
        "mma.sync.aligned.m16n8k8.row.col.f32.tf32.tf32.f32 "
        "{%0,%1,%2,%3},{%4,%5,%6,%7},{%8,%9},{%0,%1,%2,%3};"
        : "+f"(c[0]), "+f"(c[1]), "+f"(c[2]), "+f"(c[3])
        : "r"(a0), "r"(a1), "r"(a2), "r"(a3), "r"(b0), "r"(b1));
}

// ---------------------------------------------------------------------------
// tf32 tensor-core GEMM, double-buffered. Block 64x128 (8 warps x 32x32),
// 3 CTAs/SM. rna CVT staging; ABIAS / TF32OUT as in R16.
// ---------------------------------------------------------------------------
#define GBM 64
#define GBN 128
#define GBK 16

template <int AIN, int AOUT, int BMODE, int TF32OUT, int ABIAS>
__device__ __forceinline__ void gemm_tf32_body(
    const float* __restrict__ A, const float* __restrict__ W,
    const float* __restrict__ bias, const float* __restrict__ abias,
    float* __restrict__ C,
    int M, int N, int K, int bm, int bn, float oscale)
{
    __shared__ uint32_t As[2][GBM][GBK + 4];   // [2][64][20]
    __shared__ uint32_t Ws[2][GBK][GBN + 8];   // [2][16][136]

    const int t    = threadIdx.x;
    const int lane = t & 31;
    const int wid  = t >> 5;
    const int wm   = (wid & 1) * 32;
    const int wn   = (wid >> 1) * 32;

    const int a_r = t >> 2, a_c = (t & 3) * 4;   // A: 64 rows x 16, 4 fl/thread
    const int w_r = t >> 4, w_c = (t & 15) * 8;  // W: 16 rows x 128, 8 fl/thread
    const int lq = lane >> 2;
    const int lr = lane & 3;

    float c[2][4][4];
    #pragma unroll
    for (int mt = 0; mt < 2; mt++)
        #pragma unroll
        for (int nt = 0; nt < 4; nt++)
            #pragma unroll
            for (int i = 0; i < 4; i++) c[mt][nt][i] = 0.0f;

    const int NIT = K / GBK;
    const int arow = bm + a_r;
    const float* abrow = ABIAS ? (abias + (size_t)(arow >> 9) * K) : nullptr;

    {
        float4 a0 = *(const float4*)&A[(size_t)arow * K + a_c];
        if (ABIAS) {
            float4 b0 = *(const float4*)&abrow[a_c];
            a0.x = gelu_f(a0.x + b0.x); a0.y = gelu_f(a0.y + b0.y);
            a0.z = gelu_f(a0.z + b0.z); a0.w = gelu_f(a0.w + b0.w);
        } else if (AIN) {
            a0.x = gelu_f(a0.x); a0.y = gelu_f(a0.y);
            a0.z = gelu_f(a0.z); a0.w = gelu_f(a0.w);
        }
        As[0][a_r][a_c + 0] = f2tf32(a0.x); As[0][a_r][a_c + 1] = f2tf32(a0.y);
        As[0][a_r][a_c + 2] = f2tf32(a0.z); As[0][a_r][a_c + 3] = f2tf32(a0.w);

        float4 w0 = *(const float4*)&W[(size_t)w_r * N + bn + w_c];
        float4 w1 = *(const float4*)&W[(size_t)w_r * N + bn + w_c + 4];
        Ws[0][w_r][w_c + 0] = f2tf32(w0.x); Ws[0][w_r][w_c + 1] = f2tf32(w0.y);
        Ws[0][w_r][w_c + 2] = f2tf32(w0.z); Ws[0][w_r][w_c + 3] = f2tf32(w0.w);
        Ws[0][w_r][w_c + 4] = f2tf32(w1.x); Ws[0][w_r][w_c + 5] = f2tf32(w1.y);
        Ws[0][w_r][w_c + 6] = f2tf32(w1.z); Ws[0][w_r][w_c + 7] = f2tf32(w1.w);
    }
    __syncthreads();

    for (int it = 0; it < NIT; it++) {
        const int cur = it & 1, nxt = cur ^ 1;
        const bool has = (it + 1 < NIT);
        const int k0n = (it + 1) * GBK;

        float4 na0, nw0, nw1;
        if (has) {
            na0 = *(const float4*)&A[(size_t)arow * K + k0n + a_c];
            nw0 = *(const float4*)&W[(size_t)(k0n + w_r) * N + bn + w_c];
            nw1 = *(const float4*)&W[(size_t)(k0n + w_r) * N + bn + w_c + 4];
        }

        #pragma unroll
        for (int ks = 0; ks < GBK; ks += 8) {
            uint32_t af[2][4];
            #pragma unroll
            for (int mt = 0; mt < 2; mt++) {
                int r = wm + mt * 16 + lq;
                af[mt][0] = As[cur][r    ][ks + lr];
                af[mt][1] = As[cur][r + 8][ks + lr];
                af[mt][2] = As[cur][r    ][ks + lr + 4];
                af[mt][3] = As[cur][r + 8][ks + lr + 4];
            }
            uint32_t bf[4][2];
            #pragma unroll
            for (int nt = 0; nt < 4; nt++) {
                int nc = wn + nt * 8 + lq;
                bf[nt][0] = Ws[cur][ks + lr    ][nc];
                bf[nt][1] = Ws[cur][ks + lr + 4][nc];
            }
            #pragma unroll
            for (int mt = 0; mt < 2; mt++)
                #pragma unroll
                for (int nt = 0; nt < 4; nt++)
                    mma_tf32(c[mt][nt], af[mt][0], af[mt][1], af[mt][2], af[mt][3],
                             bf[nt][0], bf[nt][1]);
        }

        if (has) {
            if (ABIAS) {
                float4 b0 = *(const float4*)&abrow[k0n + a_c];
                na0.x = gelu_f(na0.x + b0.x); na0.y = gelu_f(na0.y + b0.y);
                na0.z = gelu_f(na0.z + b0.z); na0.w = gelu_f(na0.w + b0.w);
            } else if (AIN) {
                na0.x = gelu_f(na0.x); na0.y = gelu_f(na0.y);
                na0.z = gelu_f(na0.z); na0.w = gelu_f(na0.w);
            }
            As[nxt][a_r][a_c + 0] = f2tf32(na0.x); As[nxt][a_r][a_c + 1] = f2tf32(na0.y);
            As[nxt][a_r][a_c + 2] = f2tf32(na0.z); As[nxt][a_r][a_c + 3] = f2tf32(na0.w);
            Ws[nxt][w_r][w_c + 0] = f2tf32(nw0.x); Ws[nxt][w_r][w_c + 1] = f2tf32(nw0.y);
            Ws[nxt][w_r][w_c + 2] = f2tf32(nw0.z); Ws[nxt][w_r][w_c + 3] = f2tf32(nw0.w);
            Ws[nxt][w_r][w_c + 4] = f2tf32(nw1.x); Ws[nxt][w_r][w_c + 5] = f2tf32(nw1.y);
            Ws[nxt][w_r][w_c + 6] = f2tf32(nw1.z); Ws[nxt][w_r][w_c + 7] = f2tf32(nw1.w);
            __syncthreads();
        }
    }

    #pragma unroll
    for (int mt = 0; mt < 2; mt++) {
        int row0 = bm + wm + mt * 16 + lq;
        int row1 = row0 + 8;
        #pragma unroll
        for (int nt = 0; nt < 4; nt++) {
            int col = bn + wn + nt * 8 + lr * 2;
            float v0 = c[mt][nt][0], v1 = c[mt][nt][1];
            float v2 = c[mt][nt][2], v3 = c[mt][nt][3];
            if (BMODE == 1) {
                float b0 = bias[col], b1 = bias[col + 1];
                v0 += b0; v1 += b1; v2 += b0; v3 += b1;
            }
            if (BMODE == 2) {
                const float* bb0 = bias + (size_t)(row0 >> 9) * N + col;
                v0 += bb0[0]; v1 += bb0[1];
                const float* bb1 = bias + (size_t)(row1 >> 9) * N + col;
                v2 += bb1[0]; v3 += bb1[1];
            }
            if (AOUT) { v0 = gelu_f(v0); v1 = gelu_f(v1); v2 = gelu_f(v2); v3 = gelu_f(v3); }
            if (TF32OUT) {
                v0 = __uint_as_float(f2tf32(v0 * oscale));
                v1 = __uint_as_float(f2tf32(v1 * oscale));
                v2 = __uint_as_float(f2tf32(v2 * oscale));
                v3 = __uint_as_float(f2tf32(v3 * oscale));
            }
            *(float2*)&C[(size_t)row0 * N + col] = make_float2(v0, v1);
            *(float2*)&C[(size_t)row1 * N + col] = make_float2(v2, v3);
        }
    }
}

template <int AIN, int AOUT, int BMODE, int TF32OUT, int ABIAS>
__global__ __launch_bounds__(256, 3) void gemm_tf32_kernel(
    const float* __restrict__ A, const float* __restrict__ W,
    const float* __restrict__ bias, const float* __restrict__ abias,
    float* __restrict__ C, int M, int N, int K)
{
    gemm_tf32_body<AIN, AOUT, BMODE, TF32OUT, ABIAS>(A, W, bias, abias, C, M, N, K,
                                        blockIdx.x * GBM, blockIdx.y * GBN, 1.0f);
}

// QKV fused. z<3: Q/K/V projections (tf32-rounded out, Q prescaled).
// z==3 (layer-0 launch only): Hraw = gelu(E) @ W3, plain fp32 out.
__global__ __launch_bounds__(256, 3) void gemm_tf32_qkv_kernel(
    const float* __restrict__ A,
    const float* __restrict__ W0, const float* __restrict__ W1,
    const float* __restrict__ W2, const float* __restrict__ W3,
    float* __restrict__ C0, float* __restrict__ C1,
    float* __restrict__ C2, float* __restrict__ C3,
    int M, int N, int K)
{
    const int z = blockIdx.z;
    if (z == 3) {
        gemm_tf32_body<1, 0, 0, 0, 0>(A, W3, nullptr, nullptr, C3, M, N, K,
                                      blockIdx.x * GBM, blockIdx.y * GBN, 1.0f);
        return;
    }
    const float* W = (z == 0) ? W0 : (z == 1) ? W1 : W2;
    float*       C = (z == 0) ? C0 : (z == 1) ? C1 : C2;
    const float oscale = (z == 0) ? 0.17677669529663688f : 1.0f;
    gemm_tf32_body<0, 0, 0, 1, 0>(A, W, nullptr, nullptr, C, M, N, K,
                                  blockIdx.x * GBM, blockIdx.y * GBN, oscale);
}

// ---------------------------------------------------------------------------
// Fused attention v9 (unchanged) — per-key-tile QK->exp->PV, 3 CTAs/SM.
// ---------------------------------------------------------------------------
#define SCT 132
#define ATTN_SMEM_WORDS 15264
#define ATTN_SMEM_BYTES (ATTN_SMEM_WORDS * 4)

__global__ __launch_bounds__(256, 3) void attn_kernel(
    const float* __restrict__ Qp, const float* __restrict__ Kp,
    const float* __restrict__ Vp, float* __restrict__ Op)
{
    extern __shared__ uint32_t smu[];
    uint32_t* qs = smu;             // [32][36]
    uint32_t* ks = smu + 1152;      // [128][36]
    uint32_t* vs = smu + 5760;      // [128][40]
    uint32_t* sc = smu + 10880;     // [32][132]
    float*   rsp = (float*)(smu + 15104);
    float*   rs  = (float*)(smu + 15232);

    const int t    = threadIdx.x;
    const int lane = t & 31;
    const int w    = t >> 5;
    const int qb = blockIdx.x * 32;
    const int h  = blockIdx.y;
    const int b  = blockIdx.z;

    const size_t baseQ  = ((size_t)(b * NN + qb)) * DD + h * DKH;
    const size_t baseKV = ((size_t)(b * NN)) * DD + h * DKH;

    {
        int r = t >> 3, c = (t & 7) * 4;
        *(uint4*)&qs[r * 36 + c] = *(const uint4*)&Qp[baseQ + (size_t)r * DD + c];
    }
    __syncthreads();

    const int lq = lane >> 2;
    const int lr = lane & 3;
    const int mb = (w & 1) * 16;
    const int nqb = (w >> 1) * 32;
    const int nvb = (w >> 1) * 8;

    uint32_t qa[4][4];
    #pragma unroll
    for (int kk = 0; kk < 4; kk++) {
        qa[kk][0] = qs[(mb + lq)     * 36 + kk * 8 + lr];
        qa[kk][1] = qs[(mb + 8 + lq) * 36 + kk * 8 + lr];
        qa[kk][2] = qs[(mb + lq)     * 36 + kk * 8 + lr + 4];
        qa[kk][3] = qs[(mb + 8 + lq) * 36 + kk * 8 + lr + 4];
    }

    float rlo = 0.0f, rhi = 0.0f;
    float oc[4] = {0.0f, 0.0f, 0.0f, 0.0f};

    #pragma unroll 1
    for (int kt = 0; kt < 4; kt++) {
        const int kb = kt * 128;
        __syncthreads();
        for (int i = t; i < 1024; i += 256) {
            int r = i >> 3, c = (i & 7) * 4;
            *(uint4*)&ks[r * 36 + c] =
                *(const uint4*)&Kp[baseKV + (size_t)(kb + r) * DD + c];
        }
        for (int i = t; i < 1024; i += 256) {
            int r = i >> 3, c = (i & 7) * 4;
            *(uint4*)&vs[r * 40 + c] =
                *(const uint4*)&Vp[baseKV + (size_t)(kb + r) * DD + c];
        }
        __syncthreads();

        #pragma unroll
        for (int nt = 0; nt < 4; nt++) {
            const int nb = nqb + nt * 8;
            float c4[4] = {0.0f, 0.0f, 0.0f, 0.0f};
            #pragma unroll
            for (int kk = 0; kk < 4; kk++) {
                uint32_t b0 = ks[(nb + lq) * 36 + kk * 8 + lr];
                uint32_t b1 = ks[(nb + lq) * 36 + kk * 8 + lr + 4];
                mma_tf32(c4, qa[kk][0], qa[kk][1], qa[kk][2], qa[kk][3], b0, b1);
            }
            float e0 = fast_exp(c4[0]);
            float e1 = fast_exp(c4[1]);
            float e2 = fast_exp(c4[2]);
            float e3 = fast_exp(c4[3]);
            rlo += e0 + e1;
            rhi += e2 + e3;
            *(uint2*)&sc[(mb + lq)     * SCT + nb + 2 * lr] = make_uint2(f2tf32(e0), f2tf32(e1));
            *(uint2*)&sc[(mb + 8 + lq) * SCT + nb + 2 * lr] = make_uint2(f2tf32(e2), f2tf32(e3));
        }
        __syncthreads();

        #pragma unroll
        for (int kk = 0; kk < 16; kk++) {
            const int kk8 = kk * 8;
            uint32_t a0 = sc[(mb + lq)     * SCT + kk8 + lr];
            uint32_t a1 = sc[(mb + 8 + lq) * SCT + kk8 + lr];
            uint32_t a2 = sc[(mb + lq)     * SCT + kk8 + lr + 4];
            uint32_t a3 = sc[(mb + 8 + lq) * SCT + kk8 + lr + 4];
            uint32_t b0 = vs[(kk8 + lr)     * 40 + nvb + lq];
            uint32_t b1 = vs[(kk8 + lr + 4) * 40 + nvb + lq];
            mma_tf32(oc, a0, a1, a2, a3, b0, b1);
        }
    }

    rlo += __shfl_xor_sync(0xFFFFFFFFu, rlo, 1);
    rlo += __shfl_xor_sync(0xFFFFFFFFu, rlo, 2);
    rhi += __shfl_xor_sync(0xFFFFFFFFu, rhi, 1);
    rhi += __shfl_xor_sync(0xFFFFFFFFu, rhi, 2);
    if (lr == 0) {
        rsp[w * 16 + lq]     = rlo;
        rsp[w * 16 + 8 + lq] = rhi;
    }
    __syncthreads();
    if (t < 32) {
        int mt = t >> 4, r = t & 15;
        rs[t] = rsp[mt * 16 + r] + rsp[(mt + 2) * 16 + r]
              + rsp[(mt + 4) * 16 + r] + rsp[(mt + 6) * 16 + r];
    }
    __syncthreads();

    {
        float inv0 = 1.0f / rs[mb + lq];
        float inv1 = 1.0f / rs[mb + 8 + lq];
        int col = nvb + 2 * lr;
        *(float2*)&Op[baseQ + (size_t)(mb + lq)     * DD + col] =
            make_float2(oc[0] * inv0, oc[1] * inv0);
        *(float2*)&Op[baseQ + (size_t)(mb + 8 + lq) * DD + col] =
            make_float2(oc[2] * inv1, oc[3] * inv1);
    }
}

// ---------------------------------------------------------------------------
// Fused aggregate chain (unchanged).
// ---------------------------------------------------------------------------
__global__ __launch_bounds__(1024) void aggr_kernel(
    const float* __restrict__ X,
    const float* __restrict__ resW, const float* __restrict__ resb,
    const float* __restrict__ ffW1, const float* __restrict__ ffb1,
    float* __restrict__ rbias)
{
    __shared__ float part[4][DD];
    __shared__ float ag[DD];
    __shared__ float ar[DD];
    const int b = blockIdx.x;
    const int t = threadIdx.x & 255;
    const int p = threadIdx.x >> 8;

    float s = 0.0f;
    const float* base = X + (size_t)b * NN * DD + (size_t)p * 128 * DD + t;
    #pragma unroll 8
    for (int n = 0; n < 128; n++) s += base[(size_t)n * DD];
    part[p][t] = s;
    __syncthreads();
    if (p == 0)
        ag[t] = gelu_f((part[0][t] + part[1][t] + part[2][t] + part[3][t]) * (1.0f / (float)NN));
    __syncthreads();

    s = 0.0f;
    #pragma unroll 8
    for (int k = p * 64; k < p * 64 + 64; k++)
        s = fmaf(ag[k], resW[(size_t)k * DD + t], s);
    part[p][t] = s;
    __syncthreads();
    if (p == 0)
        ar[t] = gelu_f(part[0][t] + part[1][t] + part[2][t] + part[3][t] + resb[t]);
    __syncthreads();

    s = 0.0f;
    #pragma unroll 8
    for (int k = p * 64; k < p * 64 + 64; k++)
        s = fmaf(ar[k], ffW1[(size_t)k * DD + t], s);
    part[p][t] = s;
    __syncthreads();
    if (p == 0)
        rbias[b * DD + t] = part[0][t] + part[1][t] + part[2][t] + part[3][t] + ffb1[t];
}

// ---------------------------------------------------------------------------
// class_sum (unchanged).
// ---------------------------------------------------------------------------
__global__ __launch_bounds__(256) void class_sum_kernel(
    const float* __restrict__ F, const int* __restrict__ lab,
    float* __restrict__ G, float* __restrict__ CNT)
{
    __shared__ int slab[NN];
    __shared__ int idx[NN];
    __shared__ int scnt;
    const int c = blockIdx.x;
    const int b = blockIdx.y;
    const int t = threadIdx.x;

    for (int n = t; n < NN; n += 256) slab[n] = lab[b * NN + n];
    __syncthreads();

    if (t < 32) {
        int cnt = 0;
        for (int ch = 0; ch < NN / 32; ch++) {
            int n = ch * 32 + t;
            bool m = (slab[n] == c);
            unsigned mask = __ballot_sync(0xFFFFFFFFu, m);
            if (m) idx[cnt + __popc(mask & ((1u << t) - 1u))] = n;
            cnt += __popc(mask);
        }
        if (t == 0) scnt = cnt;
    }
    __syncthreads();

    const int m = scnt;
    const float* Fb = F + (size_t)b * NN * DD;
    float s = 0.0f;
    int i = 0;
    for (; i + 4 <= m; i += 4) {
        int n0 = idx[i], n1 = idx[i+1], n2 = idx[i+2], n3 = idx[i+3];
        float v0 = Fb[(size_t)n0 * DD + t];
        float v1 = Fb[(size_t)n1 * DD + t];
        float v2 = Fb[(size_t)n2 * DD + t];
        float v3 = Fb[(size_t)n3 * DD + t];
        s += (v0 + v1) + (v2 + v3);
    }
    for (; i < m; i++) s += Fb[(size_t)idx[i] * DD + t];

    G[((size_t)b * CC + c) * DD + t] = s;
    if (t == 0) CNT[b * CC + c] = (float)m;
}

// ---------------------------------------------------------------------------
// proto_out v2 (unchanged).
// ---------------------------------------------------------------------------
__global__ __launch_bounds__(256) void proto_out_kernel(
    const float* __restrict__ F, const float* __restrict__ G,
    const float* __restrict__ CNT, const int* __restrict__ lab,
    float* __restrict__ out)
{
    __shared__ float gs[CC * DD];
    __shared__ float cnt_s[CC];
    const int nb = blockIdx.x * 32;
    const int b  = blockIdx.y;
    const int t  = threadIdx.x;
    const int w  = t >> 5, lane = t & 31;

    for (int i = t; i < CC * DD; i += 256)
        gs[i] = G[(size_t)b * CC * DD + i];
    if (t < CC) cnt_s[t] = CNT[b * CC + t];
    __syncthreads();

    const float4* gs4 = (const float4*)gs;

    #pragma unroll
    for (int rr = 0; rr < 4; rr++) {
        const int n = nb + w * 4 + rr;
        const float* f = F + ((size_t)b * NN + n) * DD;
        float4 fa = *(const float4*)&f[lane * 4];
        float4 fb = *(const float4*)&f[128 + lane * 4];

        float sd = fa.x*fa.x + fa.y*fa.y + fa.z*fa.z + fa.w*fa.w
                 + fb.x*fb.x + fb.y*fb.y + fb.z*fb.z + fb.w*fb.w;

        float dp[CC];
        #pragma unroll
        for (int c = 0; c < CC; c++) {
            float4 ga = gs4[c * 64 + lane];
            float4 gb = gs4[c * 64 + 32 + lane];
            dp[c] = fa.x*ga.x + fa.y*ga.y + fa.z*ga.z + fa.w*ga.w
                  + fb.x*gb.x + fb.y*gb.y + fb.z*gb.z + fb.w*gb.w;
        }

        #pragma unroll
        for (int o = 16; o; o >>= 1) {
            sd += __shfl_xor_sync(0xFFFFFFFFu, sd, o);
            #pragma unroll
            for (int c = 0; c < CC; c++)
                dp[c] += __shfl_xor_sync(0xFFFFFFFFu, dp[c], o);
        }

        if (lane < CC) {
            const int labn = lab[b * NN + n];
            float same = (labn == lane) ? 1.0f : 0.0f;
            out[((size_t)b * NN + n) * CC + lane] =
                (dp[lane] - same * sd) / (cnt_s[lane] - same);
        }
    }
}

// ---------------------------------------------------------------------------
extern "C" void kernel_launch(void* const* d_in, const int* in_sizes, int n_in,
                              void* d_out, int out_size)
{
    const float* E    = (const float*)d_in[0];
    const int*   lab  = (const int*)  d_in[1];
    const float* Wq0  = (const float*)d_in[2];
    const float* Wk0  = (const float*)d_in[3];
    const float* Wv0  = (const float*)d_in[4];
    const float* Wo0  = (const float*)d_in[5];
    const float* Wq1  = (const float*)d_in[6];
    const float* Wk1  = (const float*)d_in[7];
    const float* Wv1  = (const float*)d_in[8];
    const float* Wo1  = (const float*)d_in[9];
    const float* resW = (const float*)d_in[10];
    const float* resb = (const float*)d_in[11];
    const float* ffW1 = (const float*)d_in[12];
    const float* ffb1 = (const float*)d_in[13];
    const float* ffW2 = (const float*)d_in[14];
    const float* ffb2 = (const float*)d_in[15];
    float* out = (float*)d_out;

    float *bQ, *bK, *bV, *bO, *bX, *bH, *rbias, *G, *CNT;
    cudaGetSymbolAddress((void**)&bQ,    g_bufQ);
    cudaGetSymbolAddress((void**)&bK,    g_bufK);
    cudaGetSymbolAddress((void**)&bV,    g_bufV);
    cudaGetSymbolAddress((void**)&bO,    g_bufO);
    cudaGetSymbolAddress((void**)&bX,    g_bufX);
    cudaGetSymbolAddress((void**)&bH,    g_bufH);
    cudaGetSymbolAddress((void**)&rbias, g_rbias);
    cudaGetSymbolAddress((void**)&G,     g_G);
    cudaGetSymbolAddress((void**)&CNT,   g_CNT);

    cudaFuncSetAttribute(attn_kernel,
                         cudaFuncAttributeMaxDynamicSharedMemorySize,
                         ATTN_SMEM_BYTES);

    const int M = BB * NN;                 // 8192
    dim3 gBig(M / GBM, DD / GBN);          // (128, 2)
    dim3 gQKV0(M / GBM, DD / GBN, 4);      // (128, 2, 4): Q,K,V + ff1-H
    dim3 gQKV1(M / GBM, DD / GBN, 3);      // (128, 2, 3)
    dim3 gAttn(NN / 32, HH, BB);           // (16, 8, 16)

    const float* ffW1hi = ffW1 + (size_t)DD * DD;

    // ---- MHA 0 (+ independent ff1 GEMM riding as z==3) ----
    gemm_tf32_qkv_kernel<<<gQKV0, 256>>>(E, Wq0, Wk0, Wv0, ffW1hi,
                                         bQ, bK, bV, bH, M, DD, DD);
    attn_kernel<<<gAttn, 256, ATTN_SMEM_BYTES>>>(bQ, bK, bV, bO);
    gemm_tf32_kernel<0, 1, 0, 0, 0><<<gBig, 256>>>(bO, Wo0, nullptr, nullptr, bX, M, DD, DD);

    // ---- MHA 1 ----
    gemm_tf32_qkv_kernel<<<gQKV1, 256>>>(bX, Wq1, Wk1, Wv1, nullptr,
                                         bQ, bK, bV, nullptr, M, DD, DD);
    attn_kernel<<<gAttn, 256, ATTN_SMEM_BYTES>>>(bQ, bK, bV, bO);
    gemm_tf32_kernel<0, 0, 0, 0, 0><<<gBig, 256>>>(bO, Wo1, nullptr, nullptr, bX, M, DD, DD);

    // ---- aggregate path ----
    aggr_kernel<<<BB, 1024>>>(bX, resW, resb, ffW1, ffb1, rbias);
    // ff2: A-staging applies gelu(H + rbias)
    gemm_tf32_kernel<0, 0, 1, 0, 1><<<gBig, 256>>>(bH, ffW2, ffb2, rbias, bK, M, DD, DD);

    // ---- prototypical scoring ----
    class_sum_kernel<<<dim3(CC, BB), 256>>>(bK, lab, G, CNT);
    proto_out_kernel<<<dim3(NN / 32, BB), 256>>>(bK, G, CNT, lab, out);
}